// round 12
// baseline (speedup 1.0000x reference)
#include <cuda_runtime.h>
#include <cstdint>

#define BS_TOK     524288            // B*S = 512*1024
#define VOCAB      100000
#define N_PRIV     8
#define MAX_CANDS  4000
#define CTX_RATE   0.15f
#define PRI_RATE   1.0f

// Output (float32, flattened, bools as 0/1):
//   obf_word | inp_word | obf_char(32*BS) | inp_pos | obf_mask | pri_mask | cpy_mask

struct TokPtrs { const void* p[6]; };

__global__ __launch_bounds__(256, 8) void alltag_fused_kernel(
    TokPtrs ptrs,
    const int4* __restrict__ lut4,       // [VOCAB][8] int4
    const int*  __restrict__ tgt_table,  // [N_POS][MAX_CANDS]
    const unsigned* __restrict__ c40a,   // counts or priv_pos
    const unsigned* __restrict__ c40b,
    float*      __restrict__ out,
    long long   out_elems)
{
    // ---------------- per-block, self-contained classification ----------------
    __shared__ unsigned smax[6];
    __shared__ int role[6];        // 0=word 1=pos 2=mask 3=ctx 4=pri 5=cand -> slot
    __shared__ int counts_pick;

    const int warpid = threadIdx.x >> 5;
    const int lane   = threadIdx.x & 31;

    if (threadIdx.x < 6) smax[threadIdx.x] = 0u;
    __syncthreads();
    {
        const int s = threadIdx.x;                    // 256 samples/block
        #pragma unroll
        for (int b = 0; b < 6; ++b) {
            unsigned v = ((const unsigned*)ptrs.p[b])[s];
            unsigned wm = __reduce_max_sync(0xffffffffu, v);
            if (lane == 0) atomicMax(&smax[b], wm);
        }
    }
    __syncthreads();
    if (threadIdx.x == 0) {
        int wslot = -1, pslot = -1, mslot = -1;
        int fs[3]; int nf = 0;
        #pragma unroll
        for (int b = 0; b < 6; ++b) {
            unsigned m = smax[b];
            if      (m <= 1u)        mslot = b;
            else if (m <= 63u)       pslot = b;
            else if (m <= (1u<<20))  wslot = b;
            else if (nf < 3)         fs[nf++] = b;
        }
        if (wslot < 0) wslot = 0;
        if (pslot < 0) pslot = 1;
        if (mslot < 0) mslot = 2;
        while (nf < 3) { fs[nf] = fs[nf ? nf-1 : 0]; ++nf; }

        int ctx, pri, cand;
        if (wslot == 0 && pslot == 1 && mslot == 2)      { ctx = 3; pri = 4; cand = 5; }
        else if (mslot == 2 && pslot == 3 && wslot == 4) { cand = 0; ctx = 1; pri = 5; }
        else if (wslot == 5 && pslot == 4 && mslot == 3) { cand = 0; pri = 1; ctx = 2; }
        else { ctx = fs[0]; pri = fs[1]; cand = fs[2]; }
        role[0] = wslot; role[1] = pslot; role[2] = mslot;
        role[3] = ctx;   role[4] = pri;   role[5] = cand;

        unsigned ma = 0u, mb = 0u;
        for (int i = 0; i < 10; ++i) { ma = max(ma, c40a[i]); mb = max(mb, c40b[i]); }
        bool a_is = (ma >= 2u && ma <= 4095u);
        bool b_is = (mb >= 2u && mb <= 4095u);
        counts_pick = (a_is || !b_is) ? 0 : 1;
    }
    __syncthreads();

    const int* __restrict__ inp_word = (const int*)  ptrs.p[role[0]];
    const int* __restrict__ inp_pos  = (const int*)  ptrs.p[role[1]];
    const int* __restrict__ inp_mask = (const int*)  ptrs.p[role[2]];
    const float* __restrict__ ctx_rand = (const float*)ptrs.p[role[3]];
    const float* __restrict__ pri_rand = (const float*)ptrs.p[role[4]];
    const float* __restrict__ cand_u   = (const float*)ptrs.p[role[5]];
    const int* __restrict__ counts = (const int*)(counts_pick == 0 ? c40a : c40b);

    // ------- 2 tokens per thread; warp owns 64 consecutive tokens -------------
    const int warp_tok0 = (blockIdx.x * 8 + warpid) * 64;

    const long long BS = BS_TOK;
    const bool has_char = (34 * BS <= out_elems);
    const long long tail0 = has_char ? 34 * BS : 2 * BS;

    // ---- front-batched loads (MLP) ----
    const int t0 = warp_tok0 + lane;
    const int t1 = warp_tok0 + 32 + lane;
    const int   w0 = inp_word[t0],  w1 = inp_word[t1];
    int         p0 = inp_pos[t0],   p1 = inp_pos[t1];
    const float cr0 = ctx_rand[t0], cr1 = ctx_rand[t1];
    const float pr0 = pri_rand[t0], pr1 = pri_rand[t1];
    const float cu0 = cand_u[t0],   cu1 = cand_u[t1];
    const int   im0 = inp_mask[t0], im1 = inp_mask[t1];

    p0 = min(max(p0, 0), 39);
    p1 = min(max(p1, 0), 39);
    const bool pri0 = (p0 < N_PRIV),           pri1 = (p1 < N_PRIV);
    const bool obf0 = pri0 ? (pr0 < PRI_RATE) : (cr0 < CTX_RATE);
    const bool obf1 = pri1 ? (pr1 < PRI_RATE) : (cr1 < CTX_RATE);

    const int cnt0 = counts[p0], cnt1 = counts[p1];
    int i0 = (int)(cu0 * (float)cnt0);           // f32 RN mul + trunc == XLA
    int i1 = (int)(cu1 * (float)cnt1);
    i0 = min(min(i0, cnt0 - 1), MAX_CANDS - 1);  i0 = max(i0, 0);
    i1 = min(min(i1, cnt1 - 1), MAX_CANDS - 1);  i1 = max(i1, 0);
    const int cdt0 = tgt_table[p0 * MAX_CANDS + i0];
    const int cdt1 = tgt_table[p1 * MAX_CANDS + i1];

    const int ow0 = obf0 ? cdt0 : w0;
    const int ow1 = obf1 ? cdt1 : w1;

    // ---- guarded scalar stores (plain write-back: let L2 buffer the output) --
    if (1 * BS <= out_elems) { out[t0] = (float)ow0; out[t1] = (float)ow1; }
    if (2 * BS <= out_elems) { out[BS_TOK + t0] = (float)w0;
                               out[BS_TOK + t1] = (float)w1; }
    if (tail0 + 1 * BS <= out_elems) { out[tail0 + t0] = (float)p0;
                                       out[tail0 + t1] = (float)p1; }
    if (tail0 + 2 * BS <= out_elems) { out[tail0 + BS_TOK + t0] = obf0 ? 1.f : 0.f;
                                       out[tail0 + BS_TOK + t1] = obf1 ? 1.f : 0.f; }
    if (tail0 + 3 * BS <= out_elems) { out[tail0 + 2*BS_TOK + t0] = pri0 ? 1.f : 0.f;
                                       out[tail0 + 2*BS_TOK + t1] = pri1 ? 1.f : 0.f; }
    if (tail0 + 4 * BS <= out_elems) {
        out[tail0 + 3*BS_TOK + t0] = (im0 != 0 && w0 == ow0) ? 1.f : 0.f;
        out[tail0 + 3*BS_TOK + t1] = (im1 != 0 && w1 == ow1) ? 1.f : 0.f;
    }

    // ---- warp-cooperative char gather (R9 structure, plain stores) -----------
    // Per iteration the warp moves 4 tokens x 128B: sub = lane>>3 picks the
    // token in the group of 4, j = lane&7 picks the 16B chunk within the row.
    if (has_char) {
        float4* __restrict__ out_char4 = (float4*)(out + 2 * BS_TOK);  // [BS][8]
        const int sub = lane >> 3;
        const int j   = lane & 7;
        #pragma unroll
        for (int q = 0; q < 2; ++q) {
            const int qbase = warp_tok0 + q * 32;
            const int owq   = q ? ow1 : ow0;
            #pragma unroll
            for (int k = 0; k < 8; ++k) {
                const int t  = k * 4 + sub;
                int ww = __shfl_sync(0xffffffffu, owq, t);
                ww = min(max(ww, 0), VOCAB - 1);
                const int4 c = __ldcg(&lut4[(size_t)ww * 8 + j]);
                float4 f;
                f.x = (float)c.x; f.y = (float)c.y;
                f.z = (float)c.z; f.w = (float)c.w;
                out_char4[(size_t)(qbase + t) * 8 + j] = f;
            }
        }
    }
}

extern "C" void kernel_launch(void* const* d_in, const int* in_sizes, int n_in,
                              void* d_out, int out_size)
{
    TokPtrs tp; int ntok = 0;
    for (int i = 0; i < 6; ++i) tp.p[i] = nullptr;
    const void* lut = nullptr; const void* tgt = nullptr;
    const void* c40[2] = {nullptr, nullptr}; int n40 = 0;

    for (int i = 0; i < n_in; ++i) {
        const long long sz = in_sizes[i];
        if (sz == BS_TOK || sz == (long long)BS_TOK * 4) {
            if (ntok < 6) tp.p[ntok++] = d_in[i];
        } else if (sz == 3200000 || sz == 12800000) lut = d_in[i];
        else if (sz == 160000 || sz == 640000)      tgt = d_in[i];
        else if (sz == 40 || sz == 160)             { if (n40 < 2) c40[n40++] = d_in[i]; }
    }
    if (ntok < 6 && n_in >= 10) {
        tp.p[0] = d_in[0]; tp.p[1] = d_in[2]; tp.p[2] = d_in[3];
        tp.p[3] = d_in[4]; tp.p[4] = d_in[5]; tp.p[5] = d_in[6];
        ntok = 6;
        if (!lut) lut = d_in[7];
        if (!tgt) tgt = d_in[8];
        if (!c40[0]) { c40[0] = d_in[9]; n40 = 1; }
    }
    while (ntok < 6) { tp.p[ntok] = tp.p[ntok ? ntok - 1 : 0]; ++ntok; }
    if (n40 == 0) { c40[0] = tgt; c40[1] = tgt; }
    else if (n40 == 1) c40[1] = c40[0];
    if (!lut) lut = d_in[0];
    if (!tgt) tgt = d_in[0];

    // 2 tokens/thread: 1024 blocks of 256 — all resident, single wave.
    alltag_fused_kernel<<<BS_TOK / 512, 256>>>(
        tp, (const int4*)lut, (const int*)tgt,
        (const unsigned*)c40[0], (const unsigned*)c40[1],
        (float*)d_out, (long long)out_size);
}

// round 13
// speedup vs baseline: 1.0010x; 1.0010x over previous
#include <cuda_runtime.h>
#include <cstdint>

#define BS_TOK     524288            // B*S = 512*1024
#define VOCAB      100000
#define N_PRIV     8
#define MAX_CANDS  4000
#define CTX_RATE   0.15f
#define PRI_RATE   1.0f

// Output (float32, flattened, bools as 0/1):
//   obf_word | inp_word | obf_char(32*BS) | inp_pos | obf_mask | pri_mask | cpy_mask

struct TokPtrs { const void* p[6]; };

__global__ __launch_bounds__(256, 7) void alltag_fused_kernel(
    TokPtrs ptrs,
    const int4* __restrict__ lut4,       // [VOCAB][8] int4
    const int*  __restrict__ tgt_table,  // [N_POS][MAX_CANDS]
    const unsigned* __restrict__ c40a,   // counts or priv_pos
    const unsigned* __restrict__ c40b,
    float*      __restrict__ out,
    long long   out_elems)
{
    // dynamic smem: 8 warps x 4KB staging (256 float4 each)
    extern __shared__ float4 sbuf[];

    // ---------------- per-block, self-contained classification ----------------
    __shared__ unsigned smax[6];
    __shared__ int role[6];        // 0=word 1=pos 2=mask 3=ctx 4=pri 5=cand -> slot
    __shared__ int counts_pick;

    const int warpid = threadIdx.x >> 5;
    const int lane   = threadIdx.x & 31;

    if (threadIdx.x < 6) smax[threadIdx.x] = 0u;
    __syncthreads();
    {
        const int s = threadIdx.x;                    // 256 samples/block
        #pragma unroll
        for (int b = 0; b < 6; ++b) {
            unsigned v = ((const unsigned*)ptrs.p[b])[s];
            unsigned wm = __reduce_max_sync(0xffffffffu, v);
            if (lane == 0) atomicMax(&smax[b], wm);
        }
    }
    __syncthreads();
    if (threadIdx.x == 0) {
        int wslot = -1, pslot = -1, mslot = -1;
        int fs[3]; int nf = 0;
        #pragma unroll
        for (int b = 0; b < 6; ++b) {
            unsigned m = smax[b];
            if      (m <= 1u)        mslot = b;
            else if (m <= 63u)       pslot = b;
            else if (m <= (1u<<20))  wslot = b;
            else if (nf < 3)         fs[nf++] = b;
        }
        if (wslot < 0) wslot = 0;
        if (pslot < 0) pslot = 1;
        if (mslot < 0) mslot = 2;
        while (nf < 3) { fs[nf] = fs[nf ? nf-1 : 0]; ++nf; }

        int ctx, pri, cand;
        if (wslot == 0 && pslot == 1 && mslot == 2)      { ctx = 3; pri = 4; cand = 5; }
        else if (mslot == 2 && pslot == 3 && wslot == 4) { cand = 0; ctx = 1; pri = 5; }
        else if (wslot == 5 && pslot == 4 && mslot == 3) { cand = 0; pri = 1; ctx = 2; }
        else { ctx = fs[0]; pri = fs[1]; cand = fs[2]; }
        role[0] = wslot; role[1] = pslot; role[2] = mslot;
        role[3] = ctx;   role[4] = pri;   role[5] = cand;

        unsigned ma = 0u, mb = 0u;
        for (int i = 0; i < 10; ++i) { ma = max(ma, c40a[i]); mb = max(mb, c40b[i]); }
        bool a_is = (ma >= 2u && ma <= 4095u);
        bool b_is = (mb >= 2u && mb <= 4095u);
        counts_pick = (a_is || !b_is) ? 0 : 1;
    }
    __syncthreads();

    const int* __restrict__ inp_word = (const int*)  ptrs.p[role[0]];
    const int* __restrict__ inp_pos  = (const int*)  ptrs.p[role[1]];
    const int* __restrict__ inp_mask = (const int*)  ptrs.p[role[2]];
    const float* __restrict__ ctx_rand = (const float*)ptrs.p[role[3]];
    const float* __restrict__ pri_rand = (const float*)ptrs.p[role[4]];
    const float* __restrict__ cand_u   = (const float*)ptrs.p[role[5]];
    const int* __restrict__ counts = (const int*)(counts_pick == 0 ? c40a : c40b);

    // ------- 2 tokens per thread; warp owns 64 consecutive tokens -------------
    const int warp_tok0 = (blockIdx.x * 8 + warpid) * 64;

    const long long BS = BS_TOK;
    const bool has_char = (34 * BS <= out_elems);
    const long long tail0 = has_char ? 34 * BS : 2 * BS;

    // ---- front-batched loads (MLP) ----
    const int t0 = warp_tok0 + lane;
    const int t1 = warp_tok0 + 32 + lane;
    const int   w0 = inp_word[t0],  w1 = inp_word[t1];
    int         p0 = inp_pos[t0],   p1 = inp_pos[t1];
    const float cr0 = ctx_rand[t0], cr1 = ctx_rand[t1];
    const float pr0 = pri_rand[t0], pr1 = pri_rand[t1];
    const float cu0 = cand_u[t0],   cu1 = cand_u[t1];
    const int   im0 = inp_mask[t0], im1 = inp_mask[t1];

    p0 = min(max(p0, 0), 39);
    p1 = min(max(p1, 0), 39);
    const bool pri0 = (p0 < N_PRIV),           pri1 = (p1 < N_PRIV);
    const bool obf0 = pri0 ? (pr0 < PRI_RATE) : (cr0 < CTX_RATE);
    const bool obf1 = pri1 ? (pr1 < PRI_RATE) : (cr1 < CTX_RATE);

    const int cnt0 = counts[p0], cnt1 = counts[p1];
    int i0 = (int)(cu0 * (float)cnt0);           // f32 RN mul + trunc == XLA
    int i1 = (int)(cu1 * (float)cnt1);
    i0 = min(min(i0, cnt0 - 1), MAX_CANDS - 1);  i0 = max(i0, 0);
    i1 = min(min(i1, cnt1 - 1), MAX_CANDS - 1);  i1 = max(i1, 0);
    const int cdt0 = tgt_table[p0 * MAX_CANDS + i0];
    const int cdt1 = tgt_table[p1 * MAX_CANDS + i1];

    const int ow0 = obf0 ? cdt0 : w0;
    const int ow1 = obf1 ? cdt1 : w1;

    // ---- guarded scalar stores (streaming — proven 10us better than plain) ---
    if (1 * BS <= out_elems) { __stcs(out + t0, (float)ow0); __stcs(out + t1, (float)ow1); }
    if (2 * BS <= out_elems) { __stcs(out + BS_TOK + t0, (float)w0);
                               __stcs(out + BS_TOK + t1, (float)w1); }
    if (tail0 + 1 * BS <= out_elems) { __stcs(out + tail0 + t0, (float)p0);
                                       __stcs(out + tail0 + t1, (float)p1); }
    if (tail0 + 2 * BS <= out_elems) { __stcs(out + tail0 + BS_TOK + t0, obf0 ? 1.f : 0.f);
                                       __stcs(out + tail0 + BS_TOK + t1, obf1 ? 1.f : 0.f); }
    if (tail0 + 3 * BS <= out_elems) { __stcs(out + tail0 + 2*BS_TOK + t0, pri0 ? 1.f : 0.f);
                                       __stcs(out + tail0 + 2*BS_TOK + t1, pri1 ? 1.f : 0.f); }
    if (tail0 + 4 * BS <= out_elems) {
        __stcs(out + tail0 + 3*BS_TOK + t0, (im0 != 0 && w0 == ow0) ? 1.f : 0.f);
        __stcs(out + tail0 + 3*BS_TOK + t1, (im1 != 0 && w1 == ow1) ? 1.f : 0.f);
    }

    // ---- warp-cooperative char gather: LDG -> STS -> TMA bulk store ----------
    // Round q covers 32 tokens (4KB). Gather loads land in the warp's private
    // 4KB smem buffer via cheap STS.128, then ONE cp.async.bulk per round
    // moves 4KB smem->gmem on the TMA engine (no STG.128 on the LSU).
    if (has_char) {
        float* __restrict__ out_char = out + 2 * BS_TOK;       // [BS][32] floats
        float4* const wbuf = sbuf + warpid * 256;              // 4KB per warp
        const int sub = lane >> 3;   // token within 4-group
        const int j   = lane & 7;    // 16B chunk within 128B row

        uint32_t wbuf_addr;
        {
            uint64_t t;
            asm("cvta.to.shared.u64 %0, %1;" : "=l"(t) : "l"((const void*)wbuf));
            wbuf_addr = (uint32_t)t;
        }

        #pragma unroll
        for (int q = 0; q < 2; ++q) {
            if (q == 1) {
                // buffer reuse: ensure round-0 TMA has finished READING smem
                if (lane == 0)
                    asm volatile("cp.async.bulk.wait_group.read 0;" ::: "memory");
                __syncwarp();
            }
            const int owq = q ? ow1 : ow0;
            #pragma unroll
            for (int k = 0; k < 8; ++k) {
                const int t  = k * 4 + sub;                    // local token 0..31
                int ww = __shfl_sync(0xffffffffu, owq, t);
                ww = min(max(ww, 0), VOCAB - 1);
                const int4 c = __ldcg(&lut4[(size_t)ww * 8 + j]);
                float4 f;
                f.x = (float)c.x; f.y = (float)c.y;
                f.z = (float)c.z; f.w = (float)c.w;
                wbuf[t * 8 + j] = f;                           // STS.128
            }
            __syncwarp();
            if (lane == 0) {
                asm volatile("fence.proxy.async.shared::cta;" ::: "memory");
                const float* gdst = out_char + (size_t)(warp_tok0 + q * 32) * 32;
                asm volatile(
                    "cp.async.bulk.global.shared::cta.bulk_group [%0], [%1], %2;"
                    :: "l"(gdst), "r"(wbuf_addr), "n"(4096) : "memory");
                asm volatile("cp.async.bulk.commit_group;" ::: "memory");
            }
        }
        // writes must be complete before kernel exit
        if (lane == 0)
            asm volatile("cp.async.bulk.wait_group 0;" ::: "memory");
    }
}

extern "C" void kernel_launch(void* const* d_in, const int* in_sizes, int n_in,
                              void* d_out, int out_size)
{
    TokPtrs tp; int ntok = 0;
    for (int i = 0; i < 6; ++i) tp.p[i] = nullptr;
    const void* lut = nullptr; const void* tgt = nullptr;
    const void* c40[2] = {nullptr, nullptr}; int n40 = 0;

    for (int i = 0; i < n_in; ++i) {
        const long long sz = in_sizes[i];
        if (sz == BS_TOK || sz == (long long)BS_TOK * 4) {
            if (ntok < 6) tp.p[ntok++] = d_in[i];
        } else if (sz == 3200000 || sz == 12800000) lut = d_in[i];
        else if (sz == 160000 || sz == 640000)      tgt = d_in[i];
        else if (sz == 40 || sz == 160)             { if (n40 < 2) c40[n40++] = d_in[i]; }
    }
    if (ntok < 6 && n_in >= 10) {
        tp.p[0] = d_in[0]; tp.p[1] = d_in[2]; tp.p[2] = d_in[3];
        tp.p[3] = d_in[4]; tp.p[4] = d_in[5]; tp.p[5] = d_in[6];
        ntok = 6;
        if (!lut) lut = d_in[7];
        if (!tgt) tgt = d_in[8];
        if (!c40[0]) { c40[0] = d_in[9]; n40 = 1; }
    }
    while (ntok < 6) { tp.p[ntok] = tp.p[ntok ? ntok - 1 : 0]; ++ntok; }
    if (n40 == 0) { c40[0] = tgt; c40[1] = tgt; }
    else if (n40 == 1) c40[1] = c40[0];
    if (!lut) lut = d_in[0];
    if (!tgt) tgt = d_in[0];

    // 2 tokens/thread: 1024 blocks of 256, 32KB dynamic smem (8 x 4KB warp
    // buffers) -> 7 blocks/SM -> 1036 resident >= 1024: single wave.
    alltag_fused_kernel<<<BS_TOK / 512, 256, 32768>>>(
        tp, (const int4*)lut, (const int*)tgt,
        (const unsigned*)c40[0], (const unsigned*)c40[1],
        (float*)d_out, (long long)out_size);
}

// round 14
// speedup vs baseline: 1.6324x; 1.6308x over previous
#include <cuda_runtime.h>
#include <cstdint>

#define BS_TOK     524288            // B*S = 512*1024
#define VOCAB      100000
#define N_PRIV     8
#define MAX_CANDS  4000
#define CTX_RATE   0.15f
#define PRI_RATE   1.0f

// Output (float32, flattened, bools as 0/1):
//   obf_word | inp_word | obf_char(32*BS) | inp_pos | obf_mask | pri_mask | cpy_mask

__global__ __launch_bounds__(256, 8) void alltag_fused_kernel(
    const int*   __restrict__ inp_word,
    const int*   __restrict__ inp_pos,
    const int*   __restrict__ inp_mask,
    const float* __restrict__ ctx_rand,
    const float* __restrict__ pri_rand,
    const float* __restrict__ cand_u,
    const int4*  __restrict__ lut4,       // [VOCAB][8] int4
    const int*   __restrict__ tgt_table,  // [N_POS][MAX_CANDS]
    const int*   __restrict__ counts,     // [N_POS]
    float*       __restrict__ out,
    long long    out_elems)
{
    const int warpid = threadIdx.x >> 5;
    const int lane   = threadIdx.x & 31;

    // ------- 2 tokens per thread; warp owns 64 consecutive tokens -------------
    const int warp_tok0 = (blockIdx.x * 8 + warpid) * 64;

    const long long BS = BS_TOK;
    const bool has_char = (34 * BS <= out_elems);
    const long long tail0 = has_char ? 34 * BS : 2 * BS;

    // ---- front-batched loads (MLP) ----
    const int t0 = warp_tok0 + lane;
    const int t1 = warp_tok0 + 32 + lane;
    const int   w0 = inp_word[t0],  w1 = inp_word[t1];
    int         p0 = inp_pos[t0],   p1 = inp_pos[t1];
    const float cr0 = ctx_rand[t0], cr1 = ctx_rand[t1];
    const float pr0 = pri_rand[t0], pr1 = pri_rand[t1];
    const float cu0 = cand_u[t0],   cu1 = cand_u[t1];
    const int   im0 = inp_mask[t0], im1 = inp_mask[t1];

    p0 = min(max(p0, 0), 39);
    p1 = min(max(p1, 0), 39);
    const bool pri0 = (p0 < N_PRIV),           pri1 = (p1 < N_PRIV);
    const bool obf0 = pri0 ? (pr0 < PRI_RATE) : (cr0 < CTX_RATE);
    const bool obf1 = pri1 ? (pr1 < PRI_RATE) : (cr1 < CTX_RATE);

    const int cnt0 = counts[p0], cnt1 = counts[p1];
    int i0 = (int)(cu0 * (float)cnt0);           // f32 RN mul + trunc == XLA
    int i1 = (int)(cu1 * (float)cnt1);
    i0 = min(min(i0, cnt0 - 1), MAX_CANDS - 1);  i0 = max(i0, 0);
    i1 = min(min(i1, cnt1 - 1), MAX_CANDS - 1);  i1 = max(i1, 0);
    const int cdt0 = tgt_table[p0 * MAX_CANDS + i0];
    const int cdt1 = tgt_table[p1 * MAX_CANDS + i1];

    const int ow0 = obf0 ? cdt0 : w0;
    const int ow1 = obf1 ? cdt1 : w1;

    // ---- guarded scalar stores (streaming) ----
    if (1 * BS <= out_elems) { __stcs(out + t0, (float)ow0); __stcs(out + t1, (float)ow1); }
    if (2 * BS <= out_elems) { __stcs(out + BS_TOK + t0, (float)w0);
                               __stcs(out + BS_TOK + t1, (float)w1); }
    if (tail0 + 1 * BS <= out_elems) { __stcs(out + tail0 + t0, (float)p0);
                                       __stcs(out + tail0 + t1, (float)p1); }
    if (tail0 + 2 * BS <= out_elems) { __stcs(out + tail0 + BS_TOK + t0, obf0 ? 1.f : 0.f);
                                       __stcs(out + tail0 + BS_TOK + t1, obf1 ? 1.f : 0.f); }
    if (tail0 + 3 * BS <= out_elems) { __stcs(out + tail0 + 2*BS_TOK + t0, pri0 ? 1.f : 0.f);
                                       __stcs(out + tail0 + 2*BS_TOK + t1, pri1 ? 1.f : 0.f); }
    if (tail0 + 4 * BS <= out_elems) {
        __stcs(out + tail0 + 3*BS_TOK + t0, (im0 != 0 && w0 == ow0) ? 1.f : 0.f);
        __stcs(out + tail0 + 3*BS_TOK + t1, (im1 != 0 && w1 == ow1) ? 1.f : 0.f);
    }

    // ---- warp-cooperative char gather (R9 champion structure, unchanged) -----
    // Per iteration the warp moves 4 tokens x 128B: sub = lane>>3 picks the
    // token in the group of 4, j = lane&7 picks the 16B chunk within the row.
    if (has_char) {
        float4* __restrict__ out_char4 = (float4*)(out + 2 * BS_TOK);  // [BS][8]
        const int sub = lane >> 3;
        const int j   = lane & 7;
        #pragma unroll
        for (int q = 0; q < 2; ++q) {
            const int qbase = warp_tok0 + q * 32;
            const int owq   = q ? ow1 : ow0;
            #pragma unroll
            for (int k = 0; k < 8; ++k) {
                const int t  = k * 4 + sub;
                int ww = __shfl_sync(0xffffffffu, owq, t);
                ww = min(max(ww, 0), VOCAB - 1);
                const int4 c = __ldcg(&lut4[(size_t)ww * 8 + j]);
                float4 f;
                f.x = (float)c.x; f.y = (float)c.y;
                f.z = (float)c.z; f.w = (float)c.w;
                __stcs(&out_char4[(size_t)(qbase + t) * 8 + j], f);
            }
        }
    }
}

extern "C" void kernel_launch(void* const* d_in, const int* in_sizes, int n_in,
                              void* d_out, int out_size)
{
    // Positional identification: the six per-token buffers appear in d_in in
    // reference signature order (word, pos, mask, ctx, pri, cand); collect by
    // size to stay robust to extra/reordered non-token inputs.
    const void* tok[6]; int ntok = 0;
    const void* lut = nullptr; const void* tgt = nullptr;
    const void* c40 = nullptr;

    for (int i = 0; i < n_in; ++i) {
        const long long sz = in_sizes[i];
        if (sz == BS_TOK || sz == (long long)BS_TOK * 4) {
            if (ntok < 6) tok[ntok++] = d_in[i];
        } else if (sz == 3200000 || sz == 12800000) lut = d_in[i];
        else if (sz == 160000 || sz == 640000)      tgt = d_in[i];
        else if ((sz == 40 || sz == 160) && !c40)   c40 = d_in[i];   // first = counts
    }
    if (ntok < 6 && n_in >= 10) {
        tok[0] = d_in[0]; tok[1] = d_in[2]; tok[2] = d_in[3];
        tok[3] = d_in[4]; tok[4] = d_in[5]; tok[5] = d_in[6];
        ntok = 6;
        if (!lut) lut = d_in[7];
        if (!tgt) tgt = d_in[8];
        if (!c40) c40 = d_in[9];
    }
    while (ntok < 6) { tok[ntok] = tok[ntok ? ntok - 1 : 0]; ++ntok; }
    if (!lut) lut = d_in[0];
    if (!tgt) tgt = d_in[0];
    if (!c40) c40 = tgt;

    // 2 tokens/thread: 1024 blocks of 256 — all resident, single wave.
    alltag_fused_kernel<<<BS_TOK / 512, 256>>>(
        (const int*)tok[0], (const int*)tok[1], (const int*)tok[2],
        (const float*)tok[3], (const float*)tok[4], (const float*)tok[5],
        (const int4*)lut, (const int*)tgt, (const int*)c40,
        (float*)d_out, (long long)out_size);
}